// round 1
// baseline (speedup 1.0000x reference)
#include <cuda_runtime.h>

#define DIM 64
#define MAX_N 100000

// Scratch accumulators (static device allocation — no cudaMalloc allowed)
__device__ float g_zr[MAX_N * DIM];
__device__ float g_zi[MAX_N * DIM];

// ---------------------------------------------------------------------------
// Kernel 1: zero the accumulators (float4 stores)
// ---------------------------------------------------------------------------
__global__ void zero_kernel(int n4) {
    int i = blockIdx.x * blockDim.x + threadIdx.x;
    if (i < n4) {
        float4 z = make_float4(0.f, 0.f, 0.f, 0.f);
        reinterpret_cast<float4*>(g_zr)[i] = z;
        reinterpret_cast<float4*>(g_zi)[i] = z;
    }
}

// ---------------------------------------------------------------------------
// Kernel 2: edge scatter. One warp per edge.
//   lanes 0..15  : m_r chunk (lane*4 .. lane*4+3)  -> red.v4 into g_zr[dst]
//   lanes 16..31 : m_i chunk ((lane-16)*4 ..)      -> red.v4 into g_zi[dst]
// Gathers are fully coalesced (upper half-warp reads same addresses as lower).
// ---------------------------------------------------------------------------
__global__ void __launch_bounds__(256) edge_kernel(
    const float* __restrict__ h_real,
    const float* __restrict__ h_imag,
    const float* __restrict__ d,
    const float* __restrict__ w_real,
    const float* __restrict__ w_imag,
    const int*   __restrict__ src,
    const int*   __restrict__ dst,
    int E)
{
    int gwarp = (blockIdx.x * blockDim.x + threadIdx.x) >> 5;
    if (gwarp >= E) return;
    int lane = threadIdx.x & 31;

    int s = __ldg(&src[gwarp]);
    int t = __ldg(&dst[gwarp]);
    float dd = __ldg(&d[t]) * __ldg(&d[s]);
    float er = dd * __ldg(&w_real[gwarp]);
    float ei = dd * __ldg(&w_imag[gwarp]);

    int c = (lane & 15) * 4;  // dim offset within the 64-wide row
    const float4 hr = *reinterpret_cast<const float4*>(h_real + (size_t)s * DIM + c);
    const float4 hi = *reinterpret_cast<const float4*>(h_imag + (size_t)s * DIM + c);

    bool lower = (lane < 16);
    // m_r = er*hr - ei*hi ; m_i = ei*hr + er*hi
    float a = lower ? er : ei;
    float b = lower ? -ei : er;

    float4 m;
    m.x = fmaf(a, hr.x, b * hi.x);
    m.y = fmaf(a, hr.y, b * hi.y);
    m.z = fmaf(a, hr.z, b * hi.z);
    m.w = fmaf(a, hr.w, b * hi.w);

    float* zbase = (lower ? g_zr : g_zi) + (size_t)t * DIM + c;
    asm volatile("red.global.add.v4.f32 [%0], {%1, %2, %3, %4};"
                 :: "l"(zbase), "f"(m.x), "f"(m.y), "f"(m.z), "f"(m.w)
                 : "memory");
}

// ---------------------------------------------------------------------------
// Kernel 3: fused dual GEMM.
//   pass1: zr = Zr @ W1^T - Zi @ W2^T + (b1 - b2)
//   pass2: zi = zr @ W2^T + Zi @ W1^T + (b1 + b2)     (uses the NEW zr)
// Block = 256 threads = 64 cols (j) x 4 row-groups (g), tile = 16 rows.
// Weights in smem with stride-65 padding (conflict-free scalar reads).
// Z tiles stored k-major so each thread reads a broadcast float4 of 4 rows.
// ---------------------------------------------------------------------------
#define TILE_R 16

__global__ void __launch_bounds__(256) gemm_kernel(
    const float* __restrict__ W1,
    const float* __restrict__ b1,
    const float* __restrict__ W2,
    const float* __restrict__ b2,
    float* __restrict__ zr_out,
    float* __restrict__ zi_out,
    int n)
{
    __shared__ float W1s[64 * 65];
    __shared__ float W2s[64 * 65];
    __shared__ float ztr[64 * TILE_R];  // Zr tile, [k][r]
    __shared__ float zti[64 * TILE_R];  // Zi tile, [k][r]
    __shared__ float zrt[64 * TILE_R];  // pass1 result, [k][r]

    int tid = threadIdx.x;

    // Load weights (coalesced reads, conflict-free padded stores)
    for (int i = tid; i < 4096; i += 256) {
        int j = i >> 6, k = i & 63;
        W1s[j * 65 + k] = W1[i];
        W2s[j * 65 + k] = W2[i];
    }

    int row0 = blockIdx.x * TILE_R;
    // Load Z tiles transposed ([k][r])
    for (int i = tid; i < TILE_R * 64; i += 256) {
        int r = i >> 6, k = i & 63;
        int row = row0 + r;
        float vr = 0.f, vi = 0.f;
        if (row < n) {
            vr = g_zr[(size_t)row * DIM + k];
            vi = g_zi[(size_t)row * DIM + k];
        }
        ztr[k * TILE_R + r] = vr;
        zti[k * TILE_R + r] = vi;
    }
    __syncthreads();

    int j = tid & 63;
    int g = tid >> 6;          // 0..3 -> rows g*4 .. g*4+3 of the tile
    int rbase = g << 2;

    float b1j = __ldg(&b1[j]);
    float b2j = __ldg(&b2[j]);

    // ---- pass 1 ----
    float a0 = 0.f, a1 = 0.f, a2 = 0.f, a3 = 0.f;
    #pragma unroll 16
    for (int k = 0; k < 64; k++) {
        float w1 = W1s[j * 65 + k];
        float w2 = W2s[j * 65 + k];
        float4 zr4 = *reinterpret_cast<const float4*>(&ztr[k * TILE_R + rbase]);
        float4 zi4 = *reinterpret_cast<const float4*>(&zti[k * TILE_R + rbase]);
        a0 += zr4.x * w1 - zi4.x * w2;
        a1 += zr4.y * w1 - zi4.y * w2;
        a2 += zr4.z * w1 - zi4.z * w2;
        a3 += zr4.w * w1 - zi4.w * w2;
    }
    float c1 = b1j - b2j;
    a0 += c1; a1 += c1; a2 += c1; a3 += c1;

    // Write zr + stash transposed for pass 2
    {
        float v[4] = {a0, a1, a2, a3};
        #pragma unroll
        for (int i = 0; i < 4; i++) {
            int row = row0 + rbase + i;
            if (row < n) zr_out[(size_t)row * DIM + j] = v[i];
            zrt[j * TILE_R + rbase + i] = v[i];
        }
    }
    __syncthreads();

    // ---- pass 2 ----
    float s0 = 0.f, s1 = 0.f, s2 = 0.f, s3 = 0.f;
    #pragma unroll 16
    for (int k = 0; k < 64; k++) {
        float w1 = W1s[j * 65 + k];
        float w2 = W2s[j * 65 + k];
        float4 zr4 = *reinterpret_cast<const float4*>(&zrt[k * TILE_R + rbase]);
        float4 zi4 = *reinterpret_cast<const float4*>(&zti[k * TILE_R + rbase]);
        s0 += zr4.x * w2 + zi4.x * w1;
        s1 += zr4.y * w2 + zi4.y * w1;
        s2 += zr4.z * w2 + zi4.z * w1;
        s3 += zr4.w * w2 + zi4.w * w1;
    }
    float c2 = b1j + b2j;
    {
        float v[4] = {s0 + c2, s1 + c2, s2 + c2, s3 + c2};
        #pragma unroll
        for (int i = 0; i < 4; i++) {
            int row = row0 + rbase + i;
            if (row < n) zi_out[(size_t)row * DIM + j] = v[i];
        }
    }
}

// ---------------------------------------------------------------------------
// Launch
// ---------------------------------------------------------------------------
extern "C" void kernel_launch(void* const* d_in, const int* in_sizes, int n_in,
                              void* d_out, int out_size)
{
    const float* h_real = (const float*)d_in[0];
    const float* h_imag = (const float*)d_in[1];
    const float* d      = (const float*)d_in[2];
    const float* w_real = (const float*)d_in[3];
    const float* w_imag = (const float*)d_in[4];
    const int*   src    = (const int*)d_in[5];
    const int*   dst    = (const int*)d_in[6];
    const float* W1     = (const float*)d_in[7];
    const float* b1     = (const float*)d_in[8];
    const float* W2     = (const float*)d_in[9];
    const float* b2     = (const float*)d_in[10];

    int n = in_sizes[2];   // N_NODES
    int E = in_sizes[3];   // N_EDGES

    float* out    = (float*)d_out;
    float* zr_out = out;
    float* zi_out = out + (size_t)n * DIM;

    int n4 = n * DIM / 4;
    zero_kernel<<<(n4 + 255) / 256, 256>>>(n4);

    long long threads = (long long)E * 32;
    int blocks = (int)((threads + 255) / 256);
    edge_kernel<<<blocks, 256>>>(h_real, h_imag, d, w_real, w_imag, src, dst, E);

    gemm_kernel<<<(n + TILE_R - 1) / TILE_R, 256>>>(W1, b1, W2, b2, zr_out, zi_out, n);
}

// round 2
// speedup vs baseline: 1.2748x; 1.2748x over previous
#include <cuda_runtime.h>

#define DIM 64
#define MAX_N 100000
#define MAX_E 1600000

// ---------------------------------------------------------------------------
// Static device scratch (no cudaMalloc allowed)
// ---------------------------------------------------------------------------
__device__ float g_zr[MAX_N * DIM];
__device__ float g_zi[MAX_N * DIM];
__device__ int   g_cnt[MAX_N];       // per-node degree (histogram)
__device__ int   g_offs[MAX_N];      // exclusive prefix sum of degrees
__device__ int   g_cursor[MAX_N];    // bucket fill cursors
__device__ int   g_bsums[128];       // block sums for the scan
__device__ int   g_srcp[MAX_E];      // permuted src index
__device__ float g_erp[MAX_E];       // permuted e_real coefficient
__device__ float g_eip[MAX_E];       // permuted e_imag coefficient

// ---------------------------------------------------------------------------
// K1: zero counters + cursors
// ---------------------------------------------------------------------------
__global__ void zero_kernel(int n) {
    int i = blockIdx.x * blockDim.x + threadIdx.x;
    if (i < n) { g_cnt[i] = 0; g_cursor[i] = 0; }
}

// ---------------------------------------------------------------------------
// K2: histogram of dst
// ---------------------------------------------------------------------------
__global__ void hist_kernel(const int* __restrict__ dst, int E) {
    int e = blockIdx.x * blockDim.x + threadIdx.x;
    if (e < E) atomicAdd(&g_cnt[dst[e]], 1);
}

// ---------------------------------------------------------------------------
// K3/K4/K5: exclusive scan of g_cnt -> g_offs (blocked Hillis-Steele)
// ---------------------------------------------------------------------------
__global__ void scan1_kernel(int n) {
    __shared__ int sh[1024];
    int i = blockIdx.x * 1024 + threadIdx.x;
    int v = (i < n) ? g_cnt[i] : 0;
    sh[threadIdx.x] = v;
    __syncthreads();
    for (int off = 1; off < 1024; off <<= 1) {
        int t = (threadIdx.x >= off) ? sh[threadIdx.x - off] : 0;
        __syncthreads();
        sh[threadIdx.x] += t;
        __syncthreads();
    }
    if (i < n) g_offs[i] = sh[threadIdx.x] - v;   // exclusive
    if (threadIdx.x == 1023) g_bsums[blockIdx.x] = sh[1023];
}

__global__ void scan2_kernel(int nb) {
    __shared__ int sh[128];
    int i = threadIdx.x;
    int v = (i < nb) ? g_bsums[i] : 0;
    sh[i] = v;
    __syncthreads();
    for (int off = 1; off < 128; off <<= 1) {
        int t = (i >= off) ? sh[i - off] : 0;
        __syncthreads();
        sh[i] += t;
        __syncthreads();
    }
    if (i < nb) g_bsums[i] = sh[i] - v;           // exclusive
}

__global__ void scan3_kernel(int n) {
    int i = blockIdx.x * blockDim.x + threadIdx.x;
    if (i < n) g_offs[i] += g_bsums[i >> 10];
}

// ---------------------------------------------------------------------------
// K6: bucket scatter — place (src, e_r, e_i) into dst-grouped order
// ---------------------------------------------------------------------------
__global__ void __launch_bounds__(256) scatter_kernel(
    const float* __restrict__ d,
    const float* __restrict__ w_real,
    const float* __restrict__ w_imag,
    const int*   __restrict__ src,
    const int*   __restrict__ dst,
    int E)
{
    int e = blockIdx.x * blockDim.x + threadIdx.x;
    if (e >= E) return;
    int t = dst[e];
    int s = src[e];
    float dd = __ldg(&d[t]) * __ldg(&d[s]);
    int pos = g_offs[t] + atomicAdd(&g_cursor[t], 1);
    g_srcp[pos] = s;
    g_erp[pos]  = dd * w_real[e];
    g_eip[pos]  = dd * w_imag[e];
}

// ---------------------------------------------------------------------------
// K7: gather-accumulate. One warp per node, lane handles 2 dims.
// No atomics: each node's z row is owned by exactly one warp.
// ---------------------------------------------------------------------------
__global__ void __launch_bounds__(256) gather_kernel(
    const float* __restrict__ h_real,
    const float* __restrict__ h_imag,
    int n)
{
    int node = (blockIdx.x * blockDim.x + threadIdx.x) >> 5;
    if (node >= n) return;
    int lane = threadIdx.x & 31;
    int c = lane * 2;

    int start = g_offs[node];
    int deg   = g_cnt[node];

    float zr0 = 0.f, zr1 = 0.f, zi0 = 0.f, zi1 = 0.f;

    int k = 0;
    // 2x unrolled for memory-level parallelism
    for (; k + 2 <= deg; k += 2) {
        int p0 = start + k, p1 = start + k + 1;
        int   s0 = __ldg(&g_srcp[p0]);
        int   s1 = __ldg(&g_srcp[p1]);
        float er0 = __ldg(&g_erp[p0]), ei0 = __ldg(&g_eip[p0]);
        float er1 = __ldg(&g_erp[p1]), ei1 = __ldg(&g_eip[p1]);
        float2 hr0 = *reinterpret_cast<const float2*>(h_real + (size_t)s0 * DIM + c);
        float2 hi0 = *reinterpret_cast<const float2*>(h_imag + (size_t)s0 * DIM + c);
        float2 hr1 = *reinterpret_cast<const float2*>(h_real + (size_t)s1 * DIM + c);
        float2 hi1 = *reinterpret_cast<const float2*>(h_imag + (size_t)s1 * DIM + c);

        zr0 = fmaf(er0, hr0.x, fmaf(-ei0, hi0.x, zr0));
        zr1 = fmaf(er0, hr0.y, fmaf(-ei0, hi0.y, zr1));
        zi0 = fmaf(ei0, hr0.x, fmaf( er0, hi0.x, zi0));
        zi1 = fmaf(ei0, hr0.y, fmaf( er0, hi0.y, zi1));

        zr0 = fmaf(er1, hr1.x, fmaf(-ei1, hi1.x, zr0));
        zr1 = fmaf(er1, hr1.y, fmaf(-ei1, hi1.y, zr1));
        zi0 = fmaf(ei1, hr1.x, fmaf( er1, hi1.x, zi0));
        zi1 = fmaf(ei1, hr1.y, fmaf( er1, hi1.y, zi1));
    }
    if (k < deg) {
        int p0 = start + k;
        int   s0 = __ldg(&g_srcp[p0]);
        float er0 = __ldg(&g_erp[p0]), ei0 = __ldg(&g_eip[p0]);
        float2 hr0 = *reinterpret_cast<const float2*>(h_real + (size_t)s0 * DIM + c);
        float2 hi0 = *reinterpret_cast<const float2*>(h_imag + (size_t)s0 * DIM + c);
        zr0 = fmaf(er0, hr0.x, fmaf(-ei0, hi0.x, zr0));
        zr1 = fmaf(er0, hr0.y, fmaf(-ei0, hi0.y, zr1));
        zi0 = fmaf(ei0, hr0.x, fmaf( er0, hi0.x, zi0));
        zi1 = fmaf(ei0, hr0.y, fmaf( er0, hi0.y, zi1));
    }

    size_t o = (size_t)node * DIM + c;
    *reinterpret_cast<float2*>(g_zr + o) = make_float2(zr0, zr1);
    *reinterpret_cast<float2*>(g_zi + o) = make_float2(zi0, zi1);
}

// ---------------------------------------------------------------------------
// K8: fused dual GEMM (unchanged from round 0)
//   pass1: zr = Zr @ W1^T - Zi @ W2^T + (b1 - b2)
//   pass2: zi = zr @ W2^T + Zi @ W1^T + (b1 + b2)   (uses the NEW zr)
// ---------------------------------------------------------------------------
#define TILE_R 16

__global__ void __launch_bounds__(256) gemm_kernel(
    const float* __restrict__ W1,
    const float* __restrict__ b1,
    const float* __restrict__ W2,
    const float* __restrict__ b2,
    float* __restrict__ zr_out,
    float* __restrict__ zi_out,
    int n)
{
    __shared__ float W1s[64 * 65];
    __shared__ float W2s[64 * 65];
    __shared__ float ztr[64 * TILE_R];
    __shared__ float zti[64 * TILE_R];
    __shared__ float zrt[64 * TILE_R];

    int tid = threadIdx.x;

    for (int i = tid; i < 4096; i += 256) {
        int j = i >> 6, k = i & 63;
        W1s[j * 65 + k] = W1[i];
        W2s[j * 65 + k] = W2[i];
    }

    int row0 = blockIdx.x * TILE_R;
    for (int i = tid; i < TILE_R * 64; i += 256) {
        int r = i >> 6, k = i & 63;
        int row = row0 + r;
        float vr = 0.f, vi = 0.f;
        if (row < n) {
            vr = g_zr[(size_t)row * DIM + k];
            vi = g_zi[(size_t)row * DIM + k];
        }
        ztr[k * TILE_R + r] = vr;
        zti[k * TILE_R + r] = vi;
    }
    __syncthreads();

    int j = tid & 63;
    int g = tid >> 6;
    int rbase = g << 2;

    float b1j = __ldg(&b1[j]);
    float b2j = __ldg(&b2[j]);

    float a0 = 0.f, a1 = 0.f, a2 = 0.f, a3 = 0.f;
    #pragma unroll 16
    for (int k = 0; k < 64; k++) {
        float w1 = W1s[j * 65 + k];
        float w2 = W2s[j * 65 + k];
        float4 zr4 = *reinterpret_cast<const float4*>(&ztr[k * TILE_R + rbase]);
        float4 zi4 = *reinterpret_cast<const float4*>(&zti[k * TILE_R + rbase]);
        a0 += zr4.x * w1 - zi4.x * w2;
        a1 += zr4.y * w1 - zi4.y * w2;
        a2 += zr4.z * w1 - zi4.z * w2;
        a3 += zr4.w * w1 - zi4.w * w2;
    }
    float c1 = b1j - b2j;
    a0 += c1; a1 += c1; a2 += c1; a3 += c1;

    {
        float v[4] = {a0, a1, a2, a3};
        #pragma unroll
        for (int i = 0; i < 4; i++) {
            int row = row0 + rbase + i;
            if (row < n) zr_out[(size_t)row * DIM + j] = v[i];
            zrt[j * TILE_R + rbase + i] = v[i];
        }
    }
    __syncthreads();

    float s0 = 0.f, s1 = 0.f, s2 = 0.f, s3 = 0.f;
    #pragma unroll 16
    for (int k = 0; k < 64; k++) {
        float w1 = W1s[j * 65 + k];
        float w2 = W2s[j * 65 + k];
        float4 zr4 = *reinterpret_cast<const float4*>(&zrt[k * TILE_R + rbase]);
        float4 zi4 = *reinterpret_cast<const float4*>(&zti[k * TILE_R + rbase]);
        s0 += zr4.x * w2 + zi4.x * w1;
        s1 += zr4.y * w2 + zi4.y * w1;
        s2 += zr4.z * w2 + zi4.z * w1;
        s3 += zr4.w * w2 + zi4.w * w1;
    }
    float c2 = b1j + b2j;
    {
        float v[4] = {s0 + c2, s1 + c2, s2 + c2, s3 + c2};
        #pragma unroll
        for (int i = 0; i < 4; i++) {
            int row = row0 + rbase + i;
            if (row < n) zi_out[(size_t)row * DIM + j] = v[i];
        }
    }
}

// ---------------------------------------------------------------------------
// Launch
// ---------------------------------------------------------------------------
extern "C" void kernel_launch(void* const* d_in, const int* in_sizes, int n_in,
                              void* d_out, int out_size)
{
    const float* h_real = (const float*)d_in[0];
    const float* h_imag = (const float*)d_in[1];
    const float* d      = (const float*)d_in[2];
    const float* w_real = (const float*)d_in[3];
    const float* w_imag = (const float*)d_in[4];
    const int*   src    = (const int*)d_in[5];
    const int*   dst    = (const int*)d_in[6];
    const float* W1     = (const float*)d_in[7];
    const float* b1     = (const float*)d_in[8];
    const float* W2     = (const float*)d_in[9];
    const float* b2     = (const float*)d_in[10];

    int n = in_sizes[2];   // N_NODES
    int E = in_sizes[3];   // N_EDGES

    float* out    = (float*)d_out;
    float* zr_out = out;
    float* zi_out = out + (size_t)n * DIM;

    int nblk_n   = (n + 255) / 256;
    int nblk_e   = (E + 255) / 256;
    int nblk_s1  = (n + 1023) / 1024;

    zero_kernel<<<nblk_n, 256>>>(n);
    hist_kernel<<<nblk_e, 256>>>(dst, E);
    scan1_kernel<<<nblk_s1, 1024>>>(n);
    scan2_kernel<<<1, 128>>>(nblk_s1);
    scan3_kernel<<<nblk_n, 256>>>(n);
    scatter_kernel<<<nblk_e, 256>>>(d, w_real, w_imag, src, dst, E);

    int nblk_g = (n * 32 + 255) / 256;
    gather_kernel<<<nblk_g, 256>>>(h_real, h_imag, n);

    gemm_kernel<<<(n + TILE_R - 1) / TILE_R, 256>>>(W1, b1, W2, b2, zr_out, zi_out, n);
}